// round 1
// baseline (speedup 1.0000x reference)
#include <cuda_runtime.h>
#include <math.h>

// ---- problem constants ----
#define BX   2
#define HDIM 32
#define WDIM 32
#define CDIM 384
#define NHD  12
#define NGRP 6
#define CGRP 64     // C / NG
#define HCH  32     // C / NH
#define LDIM 1024   // H*W
#define NSD  1024   // Hk*Wk
#define HIDD 1536
#define EPSLN 1e-5f

// ---- scratch (static device globals; no allocation allowed) ----
__device__ float g_xn [BX*LDIM*CDIM];
__device__ float g_q  [BX*LDIM*CDIM];
__device__ float g_pos[BX*NGRP*NSD*2];
__device__ float g_xs [BX*NSD*CDIM];
__device__ float g_kt [BX*CDIM*NSD];   // (B, C, ns) transposed
__device__ float g_vt [BX*CDIM*NSD];
__device__ float g_ao [BX*LDIM*CDIM];
__device__ float g_x2 [BX*LDIM*CDIM];
__device__ float g_ln2[BX*LDIM*CDIM];
__device__ float g_h1 [BX*LDIM*HIDD];

// =============================== LayerNorm ===============================
__global__ void ln_kernel(const float* __restrict__ x, const float* __restrict__ w,
                          const float* __restrict__ b, float* __restrict__ out)
{
    int row = blockIdx.x;          // 2048 rows
    int t   = threadIdx.x;         // 128 threads
    const float* xr = x + row * CDIM;
    float v0 = xr[t], v1 = xr[t + 128], v2 = xr[t + 256];
    float s  = v0 + v1 + v2;
    float sq = v0*v0 + v1*v1 + v2*v2;
    __shared__ float sh[8];
    #pragma unroll
    for (int o = 16; o; o >>= 1) {
        s  += __shfl_down_sync(0xffffffffu, s,  o);
        sq += __shfl_down_sync(0xffffffffu, sq, o);
    }
    if ((t & 31) == 0) { sh[t >> 5] = s; sh[4 + (t >> 5)] = sq; }
    __syncthreads();
    __shared__ float s_mu, s_rstd;
    if (t == 0) {
        float S = sh[0] + sh[1] + sh[2] + sh[3];
        float SQ = sh[4] + sh[5] + sh[6] + sh[7];
        float mu = S / CDIM;
        s_mu = mu;
        s_rstd = rsqrtf(SQ / CDIM - mu * mu + EPSLN);
    }
    __syncthreads();
    float mu = s_mu, rstd = s_rstd;
    float* orow = out + row * CDIM;
    orow[t]       = (v0 - mu) * rstd * w[t]       + b[t];
    orow[t + 128] = (v1 - mu) * rstd * w[t + 128] + b[t + 128];
    orow[t + 256] = (v2 - mu) * rstd * w[t + 256] + b[t + 256];
}

// =============================== GEMM ===============================
// C[M,N] = A[M,K] @ W[N,K]^T + bias[N], optional epilogue.
// EPI: 0=none, 1=gelu(exact), 2=+residual
// TRANSOUT: write out[(m>>10)*N*1024 + n*1024 + (m&1023)]  (B,C,ns layout)
template<int EPI, bool TRANSOUT>
__global__ void gemm_kernel(const float* __restrict__ A, const float* __restrict__ W,
                            const float* __restrict__ bias, const float* __restrict__ res,
                            float* __restrict__ out, int M, int N, int K)
{
    __shared__ float As[16][64];
    __shared__ float Bs[16][64];
    int tid = threadIdx.x;               // 256
    int m0 = blockIdx.y * 64, n0 = blockIdx.x * 64;
    int lr = tid >> 2;                   // 0..63
    int lc = (tid & 3) * 4;              // 0,4,8,12
    const float* Ab = A + (size_t)(m0 + lr) * K + lc;
    const float* Wb = W + (size_t)(n0 + lr) * K + lc;
    int tx = tid & 15, ty = tid >> 4;
    float acc[4][4] = {};

    for (int k0 = 0; k0 < K; k0 += 16) {
        float4 av = *(const float4*)(Ab + k0);
        float4 wv = *(const float4*)(Wb + k0);
        As[lc + 0][lr] = av.x; As[lc + 1][lr] = av.y;
        As[lc + 2][lr] = av.z; As[lc + 3][lr] = av.w;
        Bs[lc + 0][lr] = wv.x; Bs[lc + 1][lr] = wv.y;
        Bs[lc + 2][lr] = wv.z; Bs[lc + 3][lr] = wv.w;
        __syncthreads();
        #pragma unroll
        for (int kk = 0; kk < 16; kk++) {
            float4 a = *(const float4*)&As[kk][ty * 4];
            float4 bv = *(const float4*)&Bs[kk][tx * 4];
            float ar[4] = {a.x, a.y, a.z, a.w};
            float br[4] = {bv.x, bv.y, bv.z, bv.w};
            #pragma unroll
            for (int i = 0; i < 4; i++)
                #pragma unroll
                for (int j = 0; j < 4; j++)
                    acc[i][j] += ar[i] * br[j];
        }
        __syncthreads();
    }

    #pragma unroll
    for (int j = 0; j < 4; j++) {
        int n = n0 + tx * 4 + j;
        float bj = bias[n];
        #pragma unroll
        for (int i = 0; i < 4; i++) {
            int m = m0 + ty * 4 + i;
            float c = acc[i][j] + bj;
            if (EPI == 1) c = 0.5f * c * (1.0f + erff(c * 0.70710678118654752f));
            if (EPI == 2) c += res[(size_t)m * N + n];
            if (TRANSOUT) out[(size_t)(m >> 10) * N * 1024 + (size_t)n * 1024 + (m & 1023)] = c;
            else          out[(size_t)m * N + n] = c;
        }
    }
}

// ========================= Offset network (fused) =========================
// depthwise 7x7 conv + LN(CG) + GELU + pointwise(2) + tanh -> pos (y,x)
__global__ void offset_kernel(const float* __restrict__ q, const float* __restrict__ dww,
                              const float* __restrict__ dwb, const float* __restrict__ lnw,
                              const float* __restrict__ lnb, const float* __restrict__ pww,
                              float* __restrict__ pos)
{
    int pix = blockIdx.x;              // BX*NGRP*1024
    int c = threadIdx.x;               // 64
    int bg = pix >> 10;
    int l  = pix & 1023;
    int y = l >> 5, x = l & 31;
    int b = bg / NGRP, g = bg % NGRP;
    int ch = g * CGRP + c;
    const float* w = dww + c * 49;
    float acc = dwb[c];
    #pragma unroll
    for (int dy = -3; dy <= 3; ++dy) {
        int yy = y + dy;
        if ((unsigned)yy >= 32u) continue;
        #pragma unroll
        for (int dx = -3; dx <= 3; ++dx) {
            int xx = x + dx;
            if ((unsigned)xx >= 32u) continue;
            acc += q[(size_t)(b * LDIM + yy * 32 + xx) * CDIM + ch] * w[(dy + 3) * 7 + (dx + 3)];
        }
    }
    // LN over 64 channels
    float s = acc, sq = acc * acc;
    #pragma unroll
    for (int o = 16; o; o >>= 1) {
        s  += __shfl_down_sync(0xffffffffu, s,  o);
        sq += __shfl_down_sync(0xffffffffu, sq, o);
    }
    __shared__ float sh[4];
    if ((c & 31) == 0) { sh[c >> 5] = s; sh[2 + (c >> 5)] = sq; }
    __syncthreads();
    float mu  = (sh[0] + sh[1]) * (1.0f / 64.0f);
    float var = (sh[2] + sh[3]) * (1.0f / 64.0f) - mu * mu;
    float r = rsqrtf(var + EPSLN);
    float o_ = (acc - mu) * r * lnw[c] + lnb[c];
    o_ = 0.5f * o_ * (1.0f + erff(o_ * 0.70710678118654752f));
    float p0 = o_ * pww[c];
    float p1 = o_ * pww[64 + c];
    #pragma unroll
    for (int o = 16; o; o >>= 1) {
        p0 += __shfl_down_sync(0xffffffffu, p0, o);
        p1 += __shfl_down_sync(0xffffffffu, p1, o);
    }
    __shared__ float ph[4];
    if ((c & 31) == 0) { ph[c >> 5] = p0; ph[2 + (c >> 5)] = p1; }
    __syncthreads();
    if (c == 0) {
        float P0 = ph[0] + ph[1];
        float P1 = ph[2] + ph[3];
        float oy = tanhf(P0) * (2.0f / 32.0f);   // orange*ORF = (1/32)*2
        float ox = tanhf(P1) * (2.0f / 32.0f);
        float py = oy + ((y + 0.5f) / 32.0f) * 2.0f - 1.0f;
        float px = ox + ((x + 0.5f) / 32.0f) * 2.0f - 1.0f;
        pos[(size_t)bg * 2048 + l * 2 + 0] = py;
        pos[(size_t)bg * 2048 + l * 2 + 1] = px;
    }
}

// ===================== Deformable bilinear sampling =====================
__global__ void sample_kernel(const float* __restrict__ xn, const float* __restrict__ pos,
                              float* __restrict__ xs)
{
    int bn = blockIdx.x;               // BX*NSD
    int c = threadIdx.x;               // 384
    int b = bn >> 10;
    int n = bn & 1023;
    int g = c >> 6;
    float py = pos[(size_t)(b * NGRP + g) * 2048 + n * 2 + 0];
    float px = pos[(size_t)(b * NGRP + g) * 2048 + n * 2 + 1];
    float fx = (px + 1.0f) * 0.5f * 31.0f;   // align_corners=True
    float fy = (py + 1.0f) * 0.5f * 31.0f;
    float x0f = floorf(fx), y0f = floorf(fy);
    int x0 = (int)x0f, y0 = (int)y0f;
    float wx = fx - x0f, wy = fy - y0f;
    const float* base = xn + (size_t)b * LDIM * CDIM + c;
    float v = 0.0f;
    if ((unsigned)x0 < 32u && (unsigned)y0 < 32u)
        v += (1 - wx) * (1 - wy) * base[(size_t)(y0 * 32 + x0) * CDIM];
    if ((unsigned)(x0 + 1) < 32u && (unsigned)y0 < 32u)
        v += wx * (1 - wy) * base[(size_t)(y0 * 32 + x0 + 1) * CDIM];
    if ((unsigned)x0 < 32u && (unsigned)(y0 + 1) < 32u)
        v += (1 - wx) * wy * base[(size_t)((y0 + 1) * 32 + x0) * CDIM];
    if ((unsigned)(x0 + 1) < 32u && (unsigned)(y0 + 1) < 32u)
        v += wx * wy * base[(size_t)((y0 + 1) * 32 + x0 + 1) * CDIM];
    xs[(size_t)bn * CDIM + c] = v;
}

// ============== Fused attention: QK + rpe bias + softmax + AV ==============
__global__ void attn_kernel(const float* __restrict__ q, const float* __restrict__ kt,
                            const float* __restrict__ vt, const float* __restrict__ pos,
                            const float* __restrict__ rpe, float* __restrict__ ao)
{
    __shared__ float s_rpe[63 * 63];
    __shared__ float s_logit[NSD];
    __shared__ float s_q[HCH];
    __shared__ float s_red[16];
    __shared__ float s_bcast[2];

    int blk = blockIdx.x;              // BX*NHD*LDIM
    int m  = blk & 1023;
    int bh = blk >> 10;
    int b  = bh / NHD;
    int hh = bh % NHD;
    int g  = hh >> 1;
    int bg = b * NGRP + g;
    int t  = threadIdx.x;              // 256

    for (int i = t; i < 63 * 63; i += 256) s_rpe[i] = rpe[hh * 3969 + i];
    if (t < HCH) s_q[t] = q[(size_t)(b * LDIM + m) * CDIM + hh * HCH + t];
    __syncthreads();

    int my = m >> 5, mx = m & 31;
    float qgy = ((my + 0.5f) / 32.0f) * 2.0f - 1.0f;
    float qgx = ((mx + 0.5f) / 32.0f) * 2.0f - 1.0f;
    const float* ktb = kt + (size_t)b * CDIM * NSD + (size_t)hh * HCH * NSD;
    const float* posb = pos + (size_t)bg * 2048;
    const float scale = rsqrtf((float)HCH);

    float lmax = -1e30f;
    #pragma unroll
    for (int it = 0; it < 4; ++it) {
        int n = t + it * 256;
        float s = 0.0f;
        #pragma unroll
        for (int d = 0; d < HCH; ++d) s += s_q[d] * ktb[(size_t)d * NSD + n];
        s *= scale;
        float py = posb[n * 2], px = posb[n * 2 + 1];
        float dy = (qgy - py) * 0.5f, dx = (qgx - px) * 0.5f;
        float fx = (dx + 1.0f) * 31.0f;     // 0.5*(63-1)
        float fy = (dy + 1.0f) * 31.0f;
        float x0f = floorf(fx), y0f = floorf(fy);
        int x0 = (int)x0f, y0 = (int)y0f;
        float wx = fx - x0f, wy = fy - y0f;
        float bias = 0.0f;
        if ((unsigned)x0 < 63u && (unsigned)y0 < 63u)           bias += (1 - wx) * (1 - wy) * s_rpe[y0 * 63 + x0];
        if ((unsigned)(x0 + 1) < 63u && (unsigned)y0 < 63u)     bias += wx * (1 - wy) * s_rpe[y0 * 63 + x0 + 1];
        if ((unsigned)x0 < 63u && (unsigned)(y0 + 1) < 63u)     bias += (1 - wx) * wy * s_rpe[(y0 + 1) * 63 + x0];
        if ((unsigned)(x0 + 1) < 63u && (unsigned)(y0 + 1) < 63u) bias += wx * wy * s_rpe[(y0 + 1) * 63 + x0 + 1];
        s += bias;
        s_logit[n] = s;
        lmax = fmaxf(lmax, s);
    }
    // block max
    #pragma unroll
    for (int o = 16; o; o >>= 1) lmax = fmaxf(lmax, __shfl_xor_sync(0xffffffffu, lmax, o));
    if ((t & 31) == 0) s_red[t >> 5] = lmax;
    __syncthreads();
    if (t == 0) {
        float v = s_red[0];
        for (int i = 1; i < 8; i++) v = fmaxf(v, s_red[i]);
        s_bcast[0] = v;
    }
    __syncthreads();
    float gmax = s_bcast[0];

    float lsum = 0.0f;
    #pragma unroll
    for (int it = 0; it < 4; ++it) {
        int n = t + it * 256;
        float e = __expf(s_logit[n] - gmax);
        s_logit[n] = e;
        lsum += e;
    }
    #pragma unroll
    for (int o = 16; o; o >>= 1) lsum += __shfl_xor_sync(0xffffffffu, lsum, o);
    if ((t & 31) == 0) s_red[t >> 5] = lsum;
    __syncthreads();
    if (t == 0) {
        float v = 0.0f;
        for (int i = 0; i < 8; i++) v += s_red[i];
        s_bcast[1] = 1.0f / v;
    }
    __syncthreads();
    float rinv = s_bcast[1];

    // AV: warp w handles channels d = w, w+8, ...
    const float* vtb = vt + (size_t)b * CDIM * NSD + (size_t)hh * HCH * NSD;
    int warp = t >> 5, lane = t & 31;
    for (int d = warp; d < HCH; d += 8) {
        const float* vr = vtb + (size_t)d * NSD;
        float acc = 0.0f;
        for (int n = lane; n < NSD; n += 32) acc += s_logit[n] * vr[n];
        #pragma unroll
        for (int o = 16; o; o >>= 1) acc += __shfl_down_sync(0xffffffffu, acc, o);
        if (lane == 0) ao[(size_t)(b * LDIM + m) * CDIM + hh * HCH + d] = acc * rinv;
    }
}

// =============================== host ===============================
extern "C" void kernel_launch(void* const* d_in, const int* in_sizes, int n_in,
                              void* d_out, int out_size)
{
    const float* x     = (const float*)d_in[0];
    const float* n1w   = (const float*)d_in[1];
    const float* n1b   = (const float*)d_in[2];
    const float* wq    = (const float*)d_in[3];
    const float* bq    = (const float*)d_in[4];
    const float* wk    = (const float*)d_in[5];
    const float* bk    = (const float*)d_in[6];
    const float* wv    = (const float*)d_in[7];
    const float* bv    = (const float*)d_in[8];
    const float* wo    = (const float*)d_in[9];
    const float* bo    = (const float*)d_in[10];
    const float* dww   = (const float*)d_in[11];
    const float* dwb   = (const float*)d_in[12];
    const float* lnw   = (const float*)d_in[13];
    const float* lnb   = (const float*)d_in[14];
    const float* pww   = (const float*)d_in[15];
    const float* rpe   = (const float*)d_in[16];
    const float* n2w   = (const float*)d_in[17];
    const float* n2b   = (const float*)d_in[18];
    const float* fc1w  = (const float*)d_in[19];
    const float* fc1b  = (const float*)d_in[20];
    const float* fc2w  = (const float*)d_in[21];
    const float* fc2b  = (const float*)d_in[22];
    float* out = (float*)d_out;

    float *p_xn, *p_q, *p_pos, *p_xs, *p_kt, *p_vt, *p_ao, *p_x2, *p_ln2, *p_h1;
    cudaGetSymbolAddress((void**)&p_xn,  g_xn);
    cudaGetSymbolAddress((void**)&p_q,   g_q);
    cudaGetSymbolAddress((void**)&p_pos, g_pos);
    cudaGetSymbolAddress((void**)&p_xs,  g_xs);
    cudaGetSymbolAddress((void**)&p_kt,  g_kt);
    cudaGetSymbolAddress((void**)&p_vt,  g_vt);
    cudaGetSymbolAddress((void**)&p_ao,  g_ao);
    cudaGetSymbolAddress((void**)&p_x2,  g_x2);
    cudaGetSymbolAddress((void**)&p_ln2, g_ln2);
    cudaGetSymbolAddress((void**)&p_h1,  g_h1);

    const int M = BX * LDIM;   // 2048

    // 1) LN1
    ln_kernel<<<M, 128>>>(x, n1w, n1b, p_xn);
    // 2) q projection
    gemm_kernel<0, false><<<dim3(CDIM / 64, M / 64), 256>>>(p_xn, wq, bq, nullptr, p_q, M, CDIM, CDIM);
    // 3) offset network -> pos
    offset_kernel<<<BX * NGRP * 1024, 64>>>(p_q, dww, dwb, lnw, lnb, pww, p_pos);
    // 4) deformable sampling
    sample_kernel<<<BX * NSD, CDIM>>>(p_xn, p_pos, p_xs);
    // 5) k, v projections (transposed output: B,C,ns)
    gemm_kernel<0, true><<<dim3(CDIM / 64, M / 64), 256>>>(p_xs, wk, bk, nullptr, p_kt, M, CDIM, CDIM);
    gemm_kernel<0, true><<<dim3(CDIM / 64, M / 64), 256>>>(p_xs, wv, bv, nullptr, p_vt, M, CDIM, CDIM);
    // 6) fused attention
    attn_kernel<<<BX * NHD * LDIM, 256>>>(p_q, p_kt, p_vt, p_pos, rpe, p_ao);
    // 7) output projection + residual
    gemm_kernel<2, false><<<dim3(CDIM / 64, M / 64), 256>>>(p_ao, wo, bo, x, p_x2, M, CDIM, CDIM);
    // 8) LN2
    ln_kernel<<<M, 128>>>(p_x2, n2w, n2b, p_ln2);
    // 9) fc1 + gelu
    gemm_kernel<1, false><<<dim3(HIDD / 64, M / 64), 256>>>(p_ln2, fc1w, fc1b, nullptr, p_h1, M, HIDD, CDIM);
    // 10) fc2 + residual -> out
    gemm_kernel<2, false><<<dim3(CDIM / 64, M / 64), 256>>>(p_h1, fc2w, fc2b, p_x2, out, M, CDIM, HIDD);
}